// round 10
// baseline (speedup 1.0000x reference)
#include <cuda_runtime.h>
#include <cstdint>

#define NUM_DENSE 13
#define NUM_SPARSE 26
#define FEAT_NUM 40000
#define FLE 1040013                       // feature length (elements)
#define BATCH 4096
#define NGROUP 6
#define GATHER_CTAS 1024                  // 4 batch rows per 256-thread CTA
#define STREAM_CTAS 512                   // 64 k-rows x 8 chunks
#define PHASE_CTAS (STREAM_CTAS + GATHER_CTAS)

// Slot-group boundaries {5,5,4,4,4,4}: bands 51/51/41/41/41/41 MB; adjacent
// pairs <= 92 MB < 126 MB L2, so phase g's band + phase g+1's prefetch coexist.
__constant__ int c_GS[NGROUP + 1] = {0, 5, 10, 14, 18, 22, 26};

// Static scratch (allocation-free).
__device__ float g_sv[(size_t)NGROUP * BATCH * 64];   // partial sv vectors
__device__ float g_sc[(size_t)NGROUP * BATCH];        // w-sum - 0.5*s2 partials
__device__ float g_sink[STREAM_CTAS];                 // DCE sink (never written)

// ---------------------------------------------------------------------------
// Streamer: sequentially read group gg's V band (64 rows x (gs1-gs0)*40000
// cols) with coalesced float4 so L2 fills happen in DRAM-friendly order.
// CTA s: k-row = s>>3, chunk (1/8 of the row-band) = s&7. ~24 unrolled trips.
// ---------------------------------------------------------------------------
__device__ __forceinline__ void stream_role(const float* __restrict__ V,
                                            int gg, int s)
{
    const int gs0 = c_GS[gg], gs1 = c_GS[gg + 1];
    const int k    = s >> 3;
    const int part = s & 7;
    const size_t nfl   = (size_t)(gs1 - gs0) * FEAT_NUM;  // 160000 or 200000
    const size_t chunk = nfl >> 3;                        // 20000 or 25000
    const size_t abs0 = (size_t)k * FLE + NUM_DENSE
                      + (size_t)gs0 * FEAT_NUM + (size_t)part * chunk;
    const size_t a0 = (abs0 + 3) & ~(size_t)3;            // 16B-align up
    const size_t a1 = (abs0 + chunk) & ~(size_t)3;        // align down
    const float4* __restrict__ p = (const float4*)V;

    float acc = 0.f;
#pragma unroll 4
    for (size_t i = (a0 >> 2) + threadIdx.x; i < (a1 >> 2); i += 256) {
        float4 v = __ldg(p + i);
        acc += v.x + v.y + v.z + v.w;
    }
    if (acc == -1.234567e37f) g_sink[s] = acc;   // never true; defeats DCE
}

// ---------------------------------------------------------------------------
// Gather for slot group [gs0,gs1): 4 batch rows per CTA; thread t=tid&63 owns
// V row k=t. Band was streamed into L2 during the previous phase.
// ---------------------------------------------------------------------------
__device__ __forceinline__ void gather_role(const int* __restrict__ sparse,
                                            const float* __restrict__ w,
                                            const float* __restrict__ V,
                                            int g, int cig)
{
    const int tid = threadIdx.x;
    const int sub = tid >> 6;                   // 0..3 batch sub-row
    const int t   = tid & 63;                   // k index
    const int b   = cig * 4 + sub;
    const int gs0 = c_GS[g];
    const int ns  = c_GS[g + 1] - gs0;          // 4 or 5 slots

    __shared__ int   cols[4][8];
    __shared__ float ssum[4][2];

    if (t < ns) {
        int idx = sparse[b * NUM_SPARSE + gs0 + t];
        cols[sub][t] = idx + NUM_DENSE + (gs0 + t) * FEAT_NUM;
    }
    __syncthreads();

    const float* __restrict__ Vrow = V + (size_t)t * FLE;

    float vv[5];
#pragma unroll
    for (int j = 0; j < 5; j++)
        vv[j] = (j < ns) ? __ldg(Vrow + cols[sub][j]) : 0.f;

    float sv = 0.f, s2 = 0.f;
#pragma unroll
    for (int j = 0; j < 5; j++) {
        sv += vv[j];
        s2 = fmaf(vv[j], vv[j], s2);
    }
    g_sv[((size_t)g * BATCH + b) * 64 + t] = sv;

    float part = -0.5f * s2;
    if (t < ns) part += __ldg(w + cols[sub][t]);   // w (4.2 MB) is L2-hot

#pragma unroll
    for (int off = 16; off > 0; off >>= 1)
        part += __shfl_down_sync(0xFFFFFFFFu, part, off);
    if ((t & 31) == 0) ssum[sub][t >> 5] = part;
    __syncthreads();
    if (t == 0) g_sc[(size_t)g * BATCH + b] = ssum[sub][0] + ssum[sub][1];
}

// ---------------------------------------------------------------------------
// Pipelined kernel. bid order (= dispatch order):
//   [stream g0] [stream g1 | gather g0] ... [stream g5 | gather g4] [gather g5]
// Streamers of phase g+1 lead the gathers of phase g within each phase window.
// ---------------------------------------------------------------------------
__global__ __launch_bounds__(256) void fm_pipe(const int* __restrict__ sparse,
                                               const float* __restrict__ w,
                                               const float* __restrict__ V)
{
    const int bid = blockIdx.x;
    if (bid < STREAM_CTAS) {
        stream_role(V, 0, bid);                       // prologue: fill band 0
        return;
    }
    const int r = bid - STREAM_CTAS;
    const int phase = r / PHASE_CTAS;
    if (phase >= NGROUP - 1) {                        // tail: gather group 5
        gather_role(sparse, w, V, NGROUP - 1, r - (NGROUP - 1) * PHASE_CTAS);
        return;
    }
    const int o = r - phase * PHASE_CTAS;
    if (o < STREAM_CTAS) stream_role(V, phase + 1, o);            // prefetch next band
    else                 gather_role(sparse, w, V, phase, o - STREAM_CTAS);
}

// ---------------------------------------------------------------------------
// Final: sum partial sv vectors, add dense contributions, square-reduce.
// ---------------------------------------------------------------------------
__global__ __launch_bounds__(256) void fm_final(const float* __restrict__ dense,
                                                const float* __restrict__ w0,
                                                const float* __restrict__ w,
                                                const float* __restrict__ V,
                                                float* __restrict__ out)
{
    const int tid = threadIdx.x;
    const int sub = tid >> 6;
    const int t   = tid & 63;
    const int b   = blockIdx.x * 4 + sub;

    __shared__ float xd[4][NUM_DENSE];
    __shared__ float ssum[4][2];

    if (t < NUM_DENSE) xd[sub][t] = dense[b * NUM_DENSE + t];
    __syncthreads();

    float sv = 0.f;
#pragma unroll
    for (int g = 0; g < NGROUP; g++)
        sv += g_sv[((size_t)g * BATCH + b) * 64 + t];

    float s2d = 0.f;
    const float* __restrict__ Vrow = V + (size_t)t * FLE;
#pragma unroll
    for (int d = 0; d < NUM_DENSE; d++) {
        float xv = xd[sub][d] * __ldg(Vrow + d);   // same 13 cols for all b
        sv += xv;
        s2d = fmaf(xv, xv, s2d);
    }

    float part = 0.5f * fmaf(sv, sv, -s2d);
    if (t < NUM_DENSE) part += xd[sub][t] * __ldg(w + t);

#pragma unroll
    for (int off = 16; off > 0; off >>= 1)
        part += __shfl_down_sync(0xFFFFFFFFu, part, off);
    if ((t & 31) == 0) ssum[sub][t >> 5] = part;
    __syncthreads();
    if (t == 0) {
        float r = w0[0] + ssum[sub][0] + ssum[sub][1];
#pragma unroll
        for (int g = 0; g < NGROUP; g++)
            r += g_sc[(size_t)g * BATCH + b];
        out[b] = r;
    }
}

extern "C" void kernel_launch(void* const* d_in, const int* in_sizes, int n_in,
                              void* d_out, int out_size)
{
    const float* dense  = (const float*)d_in[0];      // [4096,13] f32
    const int*   sparse = (const int*)d_in[1];        // [4096,26] int32
    const float* w0     = (const float*)d_in[2];      // [1]
    const float* w      = (const float*)d_in[3];      // [1040013]
    const float* V      = (const float*)d_in[4];      // [64,1040013]
    float*       out    = (float*)d_out;              // [4096]

    const int total = STREAM_CTAS + (NGROUP - 1) * PHASE_CTAS + GATHER_CTAS;
    fm_pipe<<<total, 256>>>(sparse, w, V);
    fm_final<<<BATCH / 4, 256>>>(dense, w0, w, V, out);
}

// round 12
// speedup vs baseline: 1.2131x; 1.2131x over previous
#include <cuda_runtime.h>
#include <cstdint>

#define NUM_DENSE 13
#define NUM_SPARSE 26
#define FEAT_NUM 40000
#define FLE 1040013                       // feature length (elements)
#define BATCH 4096
#define NGROUP 6
#define ROWS_PER_CTA 8
#define CTAS_PER_GROUP (BATCH / ROWS_PER_CTA)   // 512

// Slot-group boundaries {5,5,4,4,4,4}: bands 51/51/41/41/41/41 MB. With
// ~1184 resident CTAs (~2.3 groups), live footprint stays ~< L2 (126 MB).
__constant__ int c_GS[NGROUP + 1] = {0, 5, 10, 14, 18, 22, 26};

// Static scratch (allocation-free).
__device__ float g_sv[(size_t)NGROUP * BATCH * 64];   // partial sv vectors
__device__ float g_sc[(size_t)NGROUP * BATCH];        // w-sum - 0.5*s2 partials
__device__ int   g_cnt[CTAS_PER_GROUP];               // done-counters (zero-init)

// ---------------------------------------------------------------------------
// One kernel. blockIdx.x = g * CTAS_PER_GROUP + cig. Groups execute in
// near-temporal phases (bid dispatch order; one group = 512 CTAs ≈ half the
// resident set), so each group's 41-51 MB V band is DRAM-fetched once and
// reused from L2 (~3.3 touches per 128B line).
//
// CTA layout: 256 threads = 4 subrows × 64 k-threads; each thread serves two
// batch rows (sub, sub+4) -> 10 front-batched gathers in flight per thread.
//
// The 6th group-CTA to finish a row-block finalizes it (partials L2-hot).
// ---------------------------------------------------------------------------
__global__ __launch_bounds__(256) void fm_fused(const float* __restrict__ dense,
                                                const int* __restrict__ sparse,
                                                const float* __restrict__ w0,
                                                const float* __restrict__ w,
                                                const float* __restrict__ V,
                                                float* __restrict__ out)
{
    const int g   = blockIdx.x / CTAS_PER_GROUP;     // group 0..5
    const int cig = blockIdx.x % CTAS_PER_GROUP;     // row-block index
    const int tid = threadIdx.x;
    const int sub = tid >> 6;                        // 0..3
    const int t   = tid & 63;                        // k index
    const int gs0 = c_GS[g];
    const int ns  = c_GS[g + 1] - gs0;               // 4 or 5 slots

    __shared__ int   cols[ROWS_PER_CTA][8];
    __shared__ float ssum[ROWS_PER_CTA][2];
    __shared__ int   s_old;
    __shared__ float xd[ROWS_PER_CTA][NUM_DENSE];

    const int b0 = cig * ROWS_PER_CTA;

    // Index setup: tid < 64 covers 8 rows x 8 slot entries.
    if (tid < ROWS_PER_CTA * 8) {
        int r = tid >> 3, j = tid & 7;
        if (j < ns)
            cols[r][j] = sparse[(b0 + r) * NUM_SPARSE + gs0 + j]
                       + NUM_DENSE + (gs0 + j) * FEAT_NUM;
    }
    __syncthreads();

    const float* __restrict__ Vrow = V + (size_t)t * FLE;

    // Front-batch 10 gathers (2 rows x up to 5 slots).
    float va[5], vb[5];
#pragma unroll
    for (int j = 0; j < 5; j++) {
        va[j] = (j < ns) ? __ldg(Vrow + cols[sub][j])     : 0.f;
        vb[j] = (j < ns) ? __ldg(Vrow + cols[sub + 4][j]) : 0.f;
    }

    float svA = 0.f, s2A = 0.f, svB = 0.f, s2B = 0.f;
#pragma unroll
    for (int j = 0; j < 5; j++) {
        svA += va[j];  s2A = fmaf(va[j], va[j], s2A);
        svB += vb[j];  s2B = fmaf(vb[j], vb[j], s2B);
    }
    g_sv[((size_t)g * BATCH + b0 + sub    ) * 64 + t] = svA;
    g_sv[((size_t)g * BATCH + b0 + sub + 4) * 64 + t] = svB;

    // Scalar partials: first-order w gathers (L2-hot, 4.2 MB) - 0.5*s2.
    float pA = -0.5f * s2A, pB = -0.5f * s2B;
    if (t < ns) {
        pA += __ldg(w + cols[sub][t]);
        pB += __ldg(w + cols[sub + 4][t]);
    }
#pragma unroll
    for (int off = 16; off > 0; off >>= 1) {
        pA += __shfl_down_sync(0xFFFFFFFFu, pA, off);
        pB += __shfl_down_sync(0xFFFFFFFFu, pB, off);
    }
    if ((t & 31) == 0) {
        ssum[sub][t >> 5]     = pA;
        ssum[sub + 4][t >> 5] = pB;
    }
    __syncthreads();
    if (tid < ROWS_PER_CTA)
        g_sc[(size_t)g * BATCH + b0 + tid] = ssum[tid][0] + ssum[tid][1];

    // ---- completion counter: last group-CTA for this row-block finalizes ----
    if (tid == 0) {
        __threadfence();                              // release partials
        s_old = atomicAdd(&g_cnt[cig], 1);
    }
    __syncthreads();
    if (s_old != NGROUP - 1) return;
    __threadfence();                                  // acquire partials

    // Load dense inputs for the 8 rows (tid<104 covers 8x13).
    if (tid < ROWS_PER_CTA * NUM_DENSE) {
        int r = tid / NUM_DENSE, d = tid % NUM_DENSE;
        xd[r][d] = dense[(b0 + r) * NUM_DENSE + d];
    }
    if (tid == 0) g_cnt[cig] = 0;                     // reset for graph replay
    __syncthreads();

    const float w0v = __ldg(w0);
#pragma unroll
    for (int half = 0; half < 2; half++) {
        const int r = half * 4 + sub;                 // local row 0..7
        const int b = b0 + r;

        float sv = 0.f;
#pragma unroll
        for (int gg = 0; gg < NGROUP; gg++)
            sv += g_sv[((size_t)gg * BATCH + b) * 64 + t];    // L2-hot

        float s2d = 0.f;
#pragma unroll
        for (int d = 0; d < NUM_DENSE; d++) {
            float xv = xd[r][d] * __ldg(Vrow + d);    // 13 shared cols: L2-hot
            sv += xv;
            s2d = fmaf(xv, xv, s2d);
        }

        float part = 0.5f * fmaf(sv, sv, -s2d);
        if (t < NUM_DENSE) part += xd[r][t] * __ldg(w + t);

#pragma unroll
        for (int off = 16; off > 0; off >>= 1)
            part += __shfl_down_sync(0xFFFFFFFFu, part, off);
        if ((t & 31) == 0) ssum[r][t >> 5] = part;
        __syncthreads();
        if (t == 0) {
            float res = w0v + ssum[r][0] + ssum[r][1];
#pragma unroll
            for (int gg = 0; gg < NGROUP; gg++)
                res += g_sc[(size_t)gg * BATCH + b];
            out[b] = res;
        }
        __syncthreads();
    }
}

extern "C" void kernel_launch(void* const* d_in, const int* in_sizes, int n_in,
                              void* d_out, int out_size)
{
    const float* dense  = (const float*)d_in[0];      // [4096,13] f32
    const int*   sparse = (const int*)d_in[1];        // [4096,26] int32
    const float* w0     = (const float*)d_in[2];      // [1]
    const float* w      = (const float*)d_in[3];      // [1040013]
    const float* V      = (const float*)d_in[4];      // [64,1040013]
    float*       out    = (float*)d_out;              // [4096]

    fm_fused<<<NGROUP * CTAS_PER_GROUP, 256>>>(dense, sparse, w0, w, V, out);
}

// round 16
// speedup vs baseline: 1.2588x; 1.0376x over previous
#include <cuda_runtime.h>
#include <cstdint>

#define NUM_DENSE 13
#define NUM_SPARSE 26
#define FEAT_NUM 40000
#define FLE 1040013                       // feature length (elements)
#define BATCH 4096
#define NGROUP 6
#define ROWS_PER_CTA 8
#define CTAS_PER_GROUP (BATCH / ROWS_PER_CTA)   // 512

// Slot-group boundaries {5,5,4,4,4,4}: bands 51/51/41/41/41/41 MB; ~2.3
// groups co-resident (1184 of 3072 CTAs) keeps live footprint ~< L2.
__constant__ int c_GS[NGROUP + 1] = {0, 5, 10, 14, 18, 22, 26};

// Accumulators (static zero-init; final kernel re-zeroes them every launch
// so graph replays always start from zero).
__device__ float g_sv[(size_t)BATCH * 64];    // sum over slots of V[t, col]
__device__ float g_sc[BATCH];                 // sum(w[col]) - 0.5*sum(V^2)

// ---------------------------------------------------------------------------
// Phased gather. blockIdx.x = g * CTAS_PER_GROUP + cig; dispatch order gives
// temporal phasing per slot-group so each 41-51 MB band is DRAM-fetched once.
// 256 threads = 4 subrows x 64 k-threads; each thread serves rows (sub,
// sub+4): 10 V gathers + 2 w gathers all front-batched. Tail is minimal:
// FMAs, shuffle reduce, fire-and-forget REDG atomics, exit.
// ---------------------------------------------------------------------------
__global__ __launch_bounds__(256) void fm_gather(const int* __restrict__ sparse,
                                                 const float* __restrict__ w,
                                                 const float* __restrict__ V)
{
    const int g   = blockIdx.x / CTAS_PER_GROUP;
    const int cig = blockIdx.x % CTAS_PER_GROUP;
    const int tid = threadIdx.x;
    const int sub = tid >> 6;                   // 0..3
    const int t   = tid & 63;                   // k index
    const int gs0 = c_GS[g];
    const int ns  = c_GS[g + 1] - gs0;          // 4 or 5

    __shared__ int cols[ROWS_PER_CTA][8];
    const int b0 = cig * ROWS_PER_CTA;

    if (tid < ROWS_PER_CTA * 8) {
        int r = tid >> 3, j = tid & 7;
        if (j < ns)
            cols[r][j] = sparse[(b0 + r) * NUM_SPARSE + gs0 + j]
                       + NUM_DENSE + (gs0 + j) * FEAT_NUM;
    }
    __syncthreads();

    const float* __restrict__ Vrow = V + (size_t)t * FLE;

    // Front-batch 12 independent loads (10 V + 2 w).
    float va[5], vb[5];
#pragma unroll
    for (int j = 0; j < 5; j++) {
        va[j] = (j < ns) ? __ldg(Vrow + cols[sub][j])     : 0.f;
        vb[j] = (j < ns) ? __ldg(Vrow + cols[sub + 4][j]) : 0.f;
    }
    float wA = (t < ns) ? __ldg(w + cols[sub][t])     : 0.f;
    float wB = (t < ns) ? __ldg(w + cols[sub + 4][t]) : 0.f;

    float svA = 0.f, s2A = 0.f, svB = 0.f, s2B = 0.f;
#pragma unroll
    for (int j = 0; j < 5; j++) {
        svA += va[j];  s2A = fmaf(va[j], va[j], s2A);
        svB += vb[j];  s2B = fmaf(vb[j], vb[j], s2B);
    }

    // sv accumulation: REDG no-return, spread addresses, fully hidden.
    atomicAdd(&g_sv[(size_t)(b0 + sub)     * 64 + t], svA);
    atomicAdd(&g_sv[(size_t)(b0 + sub + 4) * 64 + t], svB);

    // Scalar partial: sum(w) - 0.5*sum(V^2); reduce within the two warps of
    // this (sub) pair, then one REDG per warp leader.
    float pA = fmaf(-0.5f, s2A, wA);
    float pB = fmaf(-0.5f, s2B, wB);
#pragma unroll
    for (int off = 16; off > 0; off >>= 1) {
        pA += __shfl_down_sync(0xFFFFFFFFu, pA, off);
        pB += __shfl_down_sync(0xFFFFFFFFu, pB, off);
    }
    if ((t & 31) == 0) {
        atomicAdd(&g_sc[b0 + sub],     pA);
        atomicAdd(&g_sc[b0 + sub + 4], pB);
    }
}

// ---------------------------------------------------------------------------
// Final: read accumulated sv (1 MB, L2-hot), add dense contributions, square-
// reduce, write out. Re-zeroes accumulators for the next (graph) launch.
// 8 rows per 256-thread CTA.
// ---------------------------------------------------------------------------
__global__ __launch_bounds__(256) void fm_final(const float* __restrict__ dense,
                                                const float* __restrict__ w0,
                                                const float* __restrict__ w,
                                                const float* __restrict__ V,
                                                float* __restrict__ out)
{
    const int tid = threadIdx.x;
    const int sub = tid >> 6;
    const int t   = tid & 63;
    const int b0  = blockIdx.x * ROWS_PER_CTA;

    __shared__ float xd[ROWS_PER_CTA][NUM_DENSE];
    __shared__ float ssum[ROWS_PER_CTA][2];

    if (tid < ROWS_PER_CTA * NUM_DENSE) {
        int r = tid / NUM_DENSE, d = tid % NUM_DENSE;
        xd[r][d] = dense[(b0 + r) * NUM_DENSE + d];
    }
    __syncthreads();

    const float* __restrict__ Vrow = V + (size_t)t * FLE;
    const float w0v = __ldg(w0);

#pragma unroll
    for (int half = 0; half < 2; half++) {
        const int r = half * 4 + sub;
        const int b = b0 + r;

        float sv = g_sv[(size_t)b * 64 + t];
        g_sv[(size_t)b * 64 + t] = 0.f;            // reset for next launch

        float s2d = 0.f;
#pragma unroll
        for (int d = 0; d < NUM_DENSE; d++) {
            float xv = xd[r][d] * __ldg(Vrow + d); // 13 shared cols: L2-hot
            sv += xv;
            s2d = fmaf(xv, xv, s2d);
        }

        float part = 0.5f * fmaf(sv, sv, -s2d);
        if (t < NUM_DENSE) part += xd[r][t] * __ldg(w + t);

#pragma unroll
        for (int off = 16; off > 0; off >>= 1)
            part += __shfl_down_sync(0xFFFFFFFFu, part, off);
        if ((t & 31) == 0) ssum[r][t >> 5] = part;
        __syncthreads();
        if (t == 0) {
            out[b] = w0v + g_sc[b] + ssum[r][0] + ssum[r][1];
            g_sc[b] = 0.f;                         // reset for next launch
        }
        __syncthreads();
    }
}

extern "C" void kernel_launch(void* const* d_in, const int* in_sizes, int n_in,
                              void* d_out, int out_size)
{
    const float* dense  = (const float*)d_in[0];      // [4096,13] f32
    const int*   sparse = (const int*)d_in[1];        // [4096,26] int32
    const float* w0     = (const float*)d_in[2];      // [1]
    const float* w      = (const float*)d_in[3];      // [1040013]
    const float* V      = (const float*)d_in[4];      // [64,1040013]
    float*       out    = (float*)d_out;              // [4096]

    fm_gather<<<NGROUP * CTAS_PER_GROUP, 256>>>(sparse, w, V);
    fm_final<<<BATCH / ROWS_PER_CTA, 256>>>(dense, w0, w, V, out);
}